// round 9
// baseline (speedup 1.0000x reference)
#include <cuda_runtime.h>
#include <math.h>

#define BB   32
#define SS   128
#define EE   256
#define H1   256
#define HD   512
#define VOUT 16000
#define OUTC 128

// ---------------- device scratch (static, allowed) ----------------
__device__ float g_xs[SS*BB*EE];
__device__ float g_y0[SS*BB*2*H1];
__device__ float g_Wenc0f[4*H1*(EE+H1)], g_Wenc0b[4*H1*(EE+H1)];
__device__ float g_Wenc1f[4*H1*(3*H1)],  g_Wenc1b[4*H1*(3*H1)];
__device__ float g_Wdec0[4*HD*(EE+HD)],  g_Wdec1[4*HD*(2*HD)];
__device__ float g_benc0f[4*H1], g_benc0b[4*H1], g_benc1f[4*H1], g_benc1b[4*H1];
__device__ float g_bdec0[4*HD], g_bdec1[4*HD];
__device__ float g_h0[2][BB*HD], g_h1[2][BB*HD];
__device__ float g_c0[BB*HD],    g_c1[BB*HD];
__device__ int   g_token[BB];

// ---- weight prep: row g*HH+j -> 4j+g, concat [Wih | Whh] along K ----
__global__ void k_prep(int which, const float* __restrict__ Wih,
                       const float* __restrict__ Whh, const float* __restrict__ bsrc,
                       int IN, int HH) {
    float *Wd, *bd;
    switch (which) {
        case 0: Wd=g_Wenc0f; bd=g_benc0f; break;
        case 1: Wd=g_Wenc0b; bd=g_benc0b; break;
        case 2: Wd=g_Wenc1f; bd=g_benc1f; break;
        case 3: Wd=g_Wenc1b; bd=g_benc1b; break;
        case 4: Wd=g_Wdec0;  bd=g_bdec0;  break;
        default:Wd=g_Wdec1;  bd=g_bdec1;  break;
    }
    int K = IN + HH;
    int total = 4*HH*K;
    int stride = gridDim.x * blockDim.x;
    for (int idx = blockIdx.x*blockDim.x + threadIdx.x; idx < total + 4*HH; idx += stride) {
        if (idx < total) {
            int row = idx / K, k = idx - row*K;
            int j = row >> 2, g = row & 3;
            int sr = g*HH + j;
            Wd[idx] = (k < IN) ? Wih[sr*IN + k] : Whh[sr*HH + (k - IN)];
        } else {
            int r = idx - total;
            bd[r] = bsrc[(r & 3)*HH + (r >> 2)];
        }
    }
}

// ---- init: out[:,0,:] one-hot(cls), zero states, token=cls ----
__global__ void k_init(float* __restrict__ out, const int* __restrict__ cls) {
    int c = *cls;
    const int N1 = BB*VOUT;
    const int N2 = 4*BB*HD;
    int stride = gridDim.x * blockDim.x;
    for (int idx = blockIdx.x*blockDim.x + threadIdx.x; idx < N1+N2+BB; idx += stride) {
        if (idx < N1) {
            int b = idx / VOUT, v = idx - b*VOUT;
            out[(size_t)b*OUTC*VOUT + v] = (v == c) ? 1.0f : 0.0f;
        } else if (idx < N1+N2) {
            int r = idx - N1;
            int buf = r / (BB*HD), off = r - buf*(BB*HD);
            float* p = (buf==0) ? g_h0[0] : (buf==1) ? g_h1[0] : (buf==2) ? g_c0 : g_c1;
            p[off] = 0.0f;
        } else {
            g_token[idx - N1 - N2] = c;
        }
    }
}

// ---- embedding gather -> g_xs[t][b][e] ----
__global__ void k_embed(const int* __restrict__ inp, const float* __restrict__ emb) {
    int i = blockIdx.x*256 + threadIdx.x;      // 262144 float4s
    int e4 = i & 63, b = (i >> 6) & 31, t = i >> 11;
    ((float4*)g_xs)[i] = ((const float4*)emb)[(size_t)inp[b*SS + t]*64 + e4];
}

// ---- fused LSTM step: 16 reordered rows x 32 batch, 4-way K split, cell in epilogue ----
template<int IN, int HH, bool TOK, bool WY>
__device__ __forceinline__ void lstm_core(
    const float* __restrict__ W, const float* __restrict__ bias,
    const float* __restrict__ x, const float* __restrict__ emb,
    const float* __restrict__ hin, float* __restrict__ hout,
    float* __restrict__ cbuf, float* __restrict__ y, int ystride, int jb)
{
    constexpr int K  = IN + HH;
    constexpr int SX = K + 4;                      // padded stride: 16B-aligned, odd float4 stride
    extern __shared__ float sm[];
    float4* Xs4 = (float4*)sm;                     // [32][SX/4]
    float4* Ws4 = (float4*)(sm + 32*SX);           // [16][K/4]
    const int tid = threadIdx.x;

    for (int i = tid; i < 32*IN/4; i += 512) {
        int b = i / (IN/4), k4 = i - b*(IN/4);
        float4 v;
        if (TOK) v = ((const float4*)emb)[(size_t)g_token[b]*(IN/4) + k4];
        else     v = ((const float4*)x)[b*(IN/4) + k4];
        Xs4[b*(SX/4) + k4] = v;
    }
    for (int i = tid; i < 32*HH/4; i += 512) {
        int b = i / (HH/4), k4 = i - b*(HH/4);
        Xs4[b*(SX/4) + IN/4 + k4] = ((const float4*)hin)[b*(HD/4) + k4];
    }
    {
        const float4* Wsrc = (const float4*)(W + jb*16*K);
        for (int i = tid; i < 16*K/4; i += 512) Ws4[i] = Wsrc[i];
    }
    __syncthreads();

    const int b = tid & 31, q = (tid >> 5) & 3, ks = tid >> 7;
    constexpr int KC4 = K/16;                      // float4s per K-slice
    const float4* w0 = Ws4 + (q*4+0)*(K/4);
    const float4* w1 = Ws4 + (q*4+1)*(K/4);
    const float4* w2 = Ws4 + (q*4+2)*(K/4);
    const float4* w3 = Ws4 + (q*4+3)*(K/4);
    const float4* xb = Xs4 + b*(SX/4);
    float a0=0.f, a1=0.f, a2=0.f, a3=0.f;
    const int k0 = ks*KC4;
#pragma unroll 4
    for (int k = k0; k < k0+KC4; ++k) {
        float4 xv = xb[k]; float4 u;
        u = w0[k]; a0 += u.x*xv.x + u.y*xv.y + u.z*xv.z + u.w*xv.w;
        u = w1[k]; a1 += u.x*xv.x + u.y*xv.y + u.z*xv.z + u.w*xv.w;
        u = w2[k]; a2 += u.x*xv.x + u.y*xv.y + u.z*xv.z + u.w*xv.w;
        u = w3[k]; a3 += u.x*xv.x + u.y*xv.y + u.z*xv.z + u.w*xv.w;
    }
    __syncthreads();
    float4* red = (float4*)sm;                     // overlay (compute done)
    red[ks*128 + q*32 + b] = make_float4(a0, a1, a2, a3);
    __syncthreads();

    if (tid < 128) {                               // here ks==0, (q,b) still valid
        float4 s0=red[tid], s1=red[128+tid], s2=red[256+tid], s3=red[384+tid];
        int j = jb*4 + q;
        float4 bv = ((const float4*)bias)[j];
        float gi=s0.x+s1.x+s2.x+s3.x+bv.x;
        float gf=s0.y+s1.y+s2.y+s3.y+bv.y;
        float gg=s0.z+s1.z+s2.z+s3.z+bv.z;
        float go=s0.w+s1.w+s2.w+s3.w+bv.w;
        float ig=1.f/(1.f+expf(-gi)), fg=1.f/(1.f+expf(-gf));
        float gt=tanhf(gg),           og=1.f/(1.f+expf(-go));
        float c = fg*cbuf[b*HD + j] + ig*gt;
        float h = og*tanhf(c);
        cbuf[b*HD + j] = c;
        hout[b*HD + j] = h;
        if (WY) y[b*ystride + j] = h;
    }
}

__global__ void __launch_bounds__(512) k_enc0(int t) {
    int dir = blockIdx.y, ts = dir ? (SS-1-t) : t, pr = t & 1, col = dir ? H1 : 0;
    lstm_core<EE, H1, false, true>(dir ? g_Wenc0b : g_Wenc0f, dir ? g_benc0b : g_benc0f,
        g_xs + ts*BB*EE, nullptr,
        g_h0[pr] + col, g_h0[pr^1] + col, g_c0 + col,
        g_y0 + ts*BB*2*H1 + col, 2*H1, blockIdx.x);
}
__global__ void __launch_bounds__(512) k_enc1(int t) {
    int dir = blockIdx.y, ts = dir ? (SS-1-t) : t, pr = t & 1, col = dir ? H1 : 0;
    lstm_core<2*H1, H1, false, false>(dir ? g_Wenc1b : g_Wenc1f, dir ? g_benc1b : g_benc1f,
        g_y0 + ts*BB*2*H1, nullptr,
        g_h1[pr] + col, g_h1[pr^1] + col, g_c1 + col,
        nullptr, 0, blockIdx.x);
}
__global__ void __launch_bounds__(512) k_dec0(int s, const float* __restrict__ oemb) {
    int pr = s & 1;
    lstm_core<EE, HD, true, false>(g_Wdec0, g_bdec0, nullptr, oemb,
        g_h0[pr], g_h0[pr^1], g_c0, nullptr, 0, blockIdx.x);
}
__global__ void __launch_bounds__(512) k_dec1(int s) {
    int pr = s & 1;
    lstm_core<HD, HD, false, false>(g_Wdec1, g_bdec1, g_h0[pr^1], nullptr,
        g_h1[pr], g_h1[pr^1], g_c1, nullptr, 0, blockIdx.x);
}

// ---- output projection: out[b][s][v] = h1[b]·W[v] + b[v]; 1 v/thread, 32 batch accumulators ----
__global__ void __launch_bounds__(128) k_proj(const float* __restrict__ W,
        const float* __restrict__ bias, float* __restrict__ out, int par, int s) {
    extern __shared__ float4 hs[];                 // [32][128] float4 = 32x512 floats
    const int tid = threadIdx.x;
    const float4* h4 = (const float4*)g_h1[par];
    for (int i = tid; i < 32*128; i += 128) hs[i] = h4[i];
    __syncthreads();
    int v = blockIdx.x*128 + tid;
    float acc[32];
#pragma unroll
    for (int b = 0; b < 32; b++) acc[b] = 0.f;
    const float4* wr = (const float4*)W + (size_t)v*128;
    for (int k = 0; k < 128; k++) {
        float4 w = wr[k];
#pragma unroll
        for (int b = 0; b < 32; b++) {
            float4 h = hs[b*128 + k];
            acc[b] += w.x*h.x + w.y*h.y + w.z*h.z + w.w*h.w;
        }
    }
    float bb = bias[v];
    float* o = out + (size_t)s*VOUT + v;
#pragma unroll
    for (int b = 0; b < 32; b++) o[(size_t)b*OUTC*VOUT] = acc[b] + bb;
}

// ---- argmax (first-index tie-break, matches jnp.argmax) ----
__global__ void k_argmax(const float* __restrict__ out, int s) {
    __shared__ float sv[256]; __shared__ int si[256];
    int b = blockIdx.x, tid = threadIdx.x;
    const float* row = out + (size_t)b*OUTC*VOUT + (size_t)s*VOUT;
    float best = -INFINITY; int bi = 0;
    for (int v = tid; v < VOUT; v += 256) {
        float x = row[v];
        if (x > best) { best = x; bi = v; }
    }
    sv[tid] = best; si[tid] = bi; __syncthreads();
    for (int st = 128; st > 0; st >>= 1) {
        if (tid < st) {
            float o = sv[tid+st]; int oi = si[tid+st];
            if (o > sv[tid] || (o == sv[tid] && oi < si[tid])) { sv[tid] = o; si[tid] = oi; }
        }
        __syncthreads();
    }
    if (tid == 0) g_token[b] = si[0];
}

extern "C" void kernel_launch(void* const* d_in, const int* in_sizes, int n_in,
                              void* d_out, int out_size) {
    const int*   inp    = (const int*)d_in[0];
    const int*   cls    = (const int*)d_in[1];
    const float* in_emb = (const float*)d_in[2];
    const float* oemb   = (const float*)d_in[3];
    const float* linW   = (const float*)d_in[22];
    const float* linb   = (const float*)d_in[23];
    float* out = (float*)d_out;

    // dynamic smem sizes: 32*(K+4)*4 + 16*K*4
    const int SM_E0 = 32*(512+4)*4 + 16*512*4;     // 98816
    const int SM_K768 = 32*(768+4)*4 + 16*768*4;   // 147968
    const int SM_D1 = 32*(1024+4)*4 + 16*1024*4;   // 197120
    const int SM_P = 32*512*4;                     // 65536
    cudaFuncSetAttribute(k_enc0, cudaFuncAttributeMaxDynamicSharedMemorySize, SM_E0);
    cudaFuncSetAttribute(k_enc1, cudaFuncAttributeMaxDynamicSharedMemorySize, SM_K768);
    cudaFuncSetAttribute(k_dec0, cudaFuncAttributeMaxDynamicSharedMemorySize, SM_K768);
    cudaFuncSetAttribute(k_dec1, cudaFuncAttributeMaxDynamicSharedMemorySize, SM_D1);
    cudaFuncSetAttribute(k_proj, cudaFuncAttributeMaxDynamicSharedMemorySize, SM_P);

    // weight prep (recomputed every replay; deterministic)
    k_prep<<<256,256>>>(0, (const float*)d_in[4],  (const float*)d_in[5],  (const float*)d_in[6],  EE,   H1);
    k_prep<<<256,256>>>(1, (const float*)d_in[7],  (const float*)d_in[8],  (const float*)d_in[9],  EE,   H1);
    k_prep<<<256,256>>>(2, (const float*)d_in[10], (const float*)d_in[11], (const float*)d_in[12], 2*H1, H1);
    k_prep<<<256,256>>>(3, (const float*)d_in[13], (const float*)d_in[14], (const float*)d_in[15], 2*H1, H1);
    k_prep<<<256,256>>>(4, (const float*)d_in[16], (const float*)d_in[17], (const float*)d_in[18], EE,   HD);
    k_prep<<<256,256>>>(5, (const float*)d_in[19], (const float*)d_in[20], (const float*)d_in[21], HD,   HD);

    k_init<<<512,256>>>(out, cls);
    k_embed<<<1024,256>>>(inp, in_emb);

    // encoder: layer 0 (both dirs per step), then layer 1
    for (int t = 0; t < SS; t++) k_enc0<<<dim3(64,2), 512, SM_E0>>>(t);
    for (int t = 0; t < SS; t++) k_enc1<<<dim3(64,2), 512, SM_K768>>>(t);

    // greedy decode: 127 steps, out columns 1..127
    for (int s = 0; s < OUTC-1; s++) {
        int pr = s & 1;
        k_dec0<<<128, 512, SM_K768>>>(s, oemb);
        k_dec1<<<128, 512, SM_D1>>>(s);
        k_proj<<<125, 128, SM_P>>>(linW, linb, out, pr^1, s+1);
        k_argmax<<<32, 256>>>(out, s+1);
    }
}

// round 10
// speedup vs baseline: 1.3182x; 1.3182x over previous
#include <cuda_runtime.h>
#include <math.h>

#define BB   32
#define SS   128
#define EE   256
#define H1   256
#define HD   512
#define VOUT 16000
#define OUTC 128
typedef unsigned long long ull;

// ---------------- device scratch ----------------
__device__ float g_xs[SS*BB*EE];
__device__ float g_y0[SS*BB*2*H1];
__device__ float g_Wenc0f[4*H1*(EE+H1)], g_Wenc0b[4*H1*(EE+H1)];
__device__ float g_Wenc1f[4*H1*3*H1],    g_Wenc1b[4*H1*3*H1];
__device__ float g_Wdec0[4*HD*(EE+HD)],  g_Wdec1[4*HD*2*HD];
__device__ float g_benc0f[4*H1], g_benc0b[4*H1], g_benc1f[4*H1], g_benc1b[4*H1];
__device__ float g_bdec0[4*HD], g_bdec1[4*HD];
__device__ float g_h0[2][BB*HD], g_h1[2][BB*HD];
__device__ float g_c0[BB*HD],    g_c1[BB*HD];
__device__ ull   g_amax[BB];                      // packed (mono(val)<<32)|(VOUT-1-v)
__device__ unsigned g_cntE0, g_cntE1, g_cntD;
__device__ unsigned g_flagE0, g_flagE1, g_flagD;

// ---------------- helpers ----------------
__device__ __forceinline__ void ffma2(ull& d, ull a, ull b) {
    asm("fma.rn.f32x2 %0, %1, %2, %0;" : "+l"(d) : "l"(a), "l"(b));
}
__device__ __forceinline__ float f2sum(ull p) {
    return __uint_as_float((unsigned)p) + __uint_as_float((unsigned)(p >> 32));
}
__device__ __forceinline__ float4 ldcg4(const float4* p) { return __ldcg(p); }

// grid barrier: monotonic counter + flag; counters zeroed by k_init each replay
__device__ __forceinline__ void gbar(unsigned* cnt, unsigned* flag, unsigned ph, unsigned nb) {
    __syncthreads();
    __threadfence();
    if (threadIdx.x == 0) {
        unsigned old = atomicAdd(cnt, 1u);
        if (old == ph * nb - 1u) {
            *(volatile unsigned*)flag = ph;
        } else {
            while (*(volatile unsigned*)flag < ph) __nanosleep(64);
        }
    }
    __syncthreads();
    __threadfence();
}

// ---- weight prep: row g*HH+j -> 4j+g, concat [Wih | Whh] along K ----
__global__ void k_prep(int which, const float* __restrict__ Wih,
                       const float* __restrict__ Whh, const float* __restrict__ bsrc,
                       int IN, int HH) {
    float *Wd, *bd;
    switch (which) {
        case 0: Wd=g_Wenc0f; bd=g_benc0f; break;
        case 1: Wd=g_Wenc0b; bd=g_benc0b; break;
        case 2: Wd=g_Wenc1f; bd=g_benc1f; break;
        case 3: Wd=g_Wenc1b; bd=g_benc1b; break;
        case 4: Wd=g_Wdec0;  bd=g_bdec0;  break;
        default:Wd=g_Wdec1;  bd=g_bdec1;  break;
    }
    int K = IN + HH;
    int total = 4*HH*K;
    int stride = gridDim.x * blockDim.x;
    for (int idx = blockIdx.x*blockDim.x + threadIdx.x; idx < total + 4*HH; idx += stride) {
        if (idx < total) {
            int row = idx / K, k = idx - row*K;
            int j = row >> 2, g = row & 3;
            int sr = g*HH + j;
            Wd[idx] = (k < IN) ? Wih[sr*IN + k] : Whh[sr*HH + (k - IN)];
        } else {
            int r = idx - total;
            bd[r] = bsrc[(r & 3)*HH + (r >> 2)];
        }
    }
}

// ---- init: out[:,0,:] one-hot(cls), zero states, amax slots = cls, zero barriers ----
__global__ void k_init(float* __restrict__ out, const int* __restrict__ cls) {
    int c = *cls;
    const int N1 = BB*VOUT;
    const int N2 = 4*BB*HD;
    int stride = gridDim.x * blockDim.x;
    if (blockIdx.x == 0 && threadIdx.x == 0) {
        g_cntE0 = 0; g_flagE0 = 0; g_cntE1 = 0; g_flagE1 = 0; g_cntD = 0; g_flagD = 0;
    }
    for (int idx = blockIdx.x*blockDim.x + threadIdx.x; idx < N1+N2+BB; idx += stride) {
        if (idx < N1) {
            int b = idx / VOUT, v = idx - b*VOUT;
            out[(size_t)b*OUTC*VOUT + v] = (v == c) ? 1.0f : 0.0f;
        } else if (idx < N1+N2) {
            int r = idx - N1;
            int buf = r / (BB*HD), off = r - buf*(BB*HD);
            float* p = (buf==0) ? g_h0[0] : (buf==1) ? g_h1[0] : (buf==2) ? g_c0 : g_c1;
            p[off] = 0.0f;
        } else {
            g_amax[idx - N1 - N2] = (ull)(unsigned)(VOUT - 1 - c);
        }
    }
}

// ---- embedding gather -> g_xs[t][b][e] ----
__global__ void k_embed(const int* __restrict__ inp, const float* __restrict__ emb) {
    int i = blockIdx.x*256 + threadIdx.x;      // 262144 float4s
    int e4 = i & 63, b = (i >> 6) & 31, t = i >> 13 << 7 | ((i >> 6) >> 7); // careful? no:
    // recompute cleanly:
    e4 = i & 63; b = (i >> 6) & 31; t = i >> 11;
    ((float4*)g_xs)[i] = ((const float4*)emb)[(size_t)inp[b*SS + t]*64 + e4];
}

// ---- fused LSTM phase: 16 reordered rows x 32 batch, 4-way K split, f32x2 FMA, cell epilogue ----
template<int K, bool WY>
__device__ __forceinline__ void lstm_phase(
    float* sm, const float* __restrict__ Ws, const float* __restrict__ bias, int jb,
    float* __restrict__ hout, float* __restrict__ cbuf,
    float* __restrict__ y, int ystride)
{
    constexpr int SX = K + 4;
    const int tid = threadIdx.x;
    const int b = tid & 31, q = (tid >> 5) & 3, ks = tid >> 7;
    const ulonglong2* w0 = (const ulonglong2*)(Ws + (q*4+0)*K);
    const ulonglong2* w1 = (const ulonglong2*)(Ws + (q*4+1)*K);
    const ulonglong2* w2 = (const ulonglong2*)(Ws + (q*4+2)*K);
    const ulonglong2* w3 = (const ulonglong2*)(Ws + (q*4+3)*K);
    const ulonglong2* xb = (const ulonglong2*)(sm + b*SX);
    ull a0=0, a1=0, a2=0, a3=0;
    constexpr int KC = K / 16;                 // float4 count per K-slice
    const int k0 = ks * KC;
#pragma unroll 4
    for (int k = k0; k < k0 + KC; ++k) {
        ulonglong2 xv = xb[k];
        ulonglong2 u;
        u = w0[k]; ffma2(a0, u.x, xv.x); ffma2(a0, u.y, xv.y);
        u = w1[k]; ffma2(a1, u.x, xv.x); ffma2(a1, u.y, xv.y);
        u = w2[k]; ffma2(a2, u.x, xv.x); ffma2(a2, u.y, xv.y);
        u = w3[k]; ffma2(a3, u.x, xv.x); ffma2(a3, u.y, xv.y);
    }
    __syncthreads();
    float4* red = (float4*)sm;                 // overlay Xs region (Ws untouched)
    red[ks*128 + q*32 + b] = make_float4(f2sum(a0), f2sum(a1), f2sum(a2), f2sum(a3));
    __syncthreads();
    if (tid < 128) {                           // ks==0 here; (q,b) still valid
        float4 s0=red[tid], s1=red[128+tid], s2=red[256+tid], s3=red[384+tid];
        int j = jb*4 + q;
        float4 bv = ((const float4*)bias)[j];
        float gi=s0.x+s1.x+s2.x+s3.x+bv.x;
        float gf=s0.y+s1.y+s2.y+s3.y+bv.y;
        float gg=s0.z+s1.z+s2.z+s3.z+bv.z;
        float go=s0.w+s1.w+s2.w+s3.w+bv.w;
        float ig=1.f/(1.f+expf(-gi)), fg=1.f/(1.f+expf(-gf));
        float gt=tanhf(gg),           og=1.f/(1.f+expf(-go));
        float c = fg*cbuf[b*HD + j] + ig*gt;
        float h = og*tanhf(c);
        cbuf[b*HD + j] = c;
        hout[b*HD + j] = h;
        if (WY) y[b*ystride + j] = h;
    }
}

// ---- persistent encoder layer 0: 128 blocks = 64 jb x 2 dir, W resident in SMEM ----
__global__ void __launch_bounds__(512) k_enc0p() {
    extern __shared__ float sm[];
    constexpr int SX = EE + H1 + 4;            // 516
    float* Ws = sm + 32*SX;
    const int tid = threadIdx.x, bx = blockIdx.x;
    const int jb = bx & 63, dir = bx >> 6, col = dir ? H1 : 0;
    const float* W    = dir ? g_Wenc0b : g_Wenc0f;
    const float* bias = dir ? g_benc0b : g_benc0f;
    for (int i = tid; i < 16*512/4; i += 512)
        ((float4*)Ws)[i] = ((const float4*)(W + jb*16*512))[i];
    unsigned ph = 0;
    for (int t = 0; t < SS; t++) {
        int ts = dir ? SS-1-t : t, pr = t & 1;
        const float4* x4 = (const float4*)(g_xs + ts*BB*EE);
        const float4* h4 = (const float4*)(g_h0[pr]);
        for (int i = tid; i < 32*64; i += 512) {
            int b = i >> 6, k = i & 63;
            ((float4*)(sm + b*SX))[k] = x4[b*64 + k];
        }
        for (int i = tid; i < 32*64; i += 512) {
            int b = i >> 6, k = i & 63;
            ((float4*)(sm + b*SX))[64 + k] = ldcg4(h4 + b*(HD/4) + col/4 + k);
        }
        __syncthreads();
        lstm_phase<512, true>(sm, Ws, bias, jb, g_h0[pr^1] + col, g_c0 + col,
                              g_y0 + ts*BB*2*H1 + col, 2*H1);
        ph++; gbar(&g_cntE0, &g_flagE0, ph, 128);
    }
}

// ---- persistent encoder layer 1 ----
__global__ void __launch_bounds__(512) k_enc1p() {
    extern __shared__ float sm[];
    constexpr int SX = 2*H1 + H1 + 4;          // 772
    float* Ws = sm + 32*SX;
    const int tid = threadIdx.x, bx = blockIdx.x;
    const int jb = bx & 63, dir = bx >> 6, col = dir ? H1 : 0;
    const float* W    = dir ? g_Wenc1b : g_Wenc1f;
    const float* bias = dir ? g_benc1b : g_benc1f;
    for (int i = tid; i < 16*768/4; i += 512)
        ((float4*)Ws)[i] = ((const float4*)(W + jb*16*768))[i];
    unsigned ph = 0;
    for (int t = 0; t < SS; t++) {
        int ts = dir ? SS-1-t : t, pr = t & 1;
        const float4* x4 = (const float4*)(g_y0 + ts*BB*2*H1);
        const float4* h4 = (const float4*)(g_h1[pr]);
        for (int i = tid; i < 32*128; i += 512) {
            int b = i >> 7, k = i & 127;
            ((float4*)(sm + b*SX))[k] = x4[b*128 + k];
        }
        for (int i = tid; i < 32*64; i += 512) {
            int b = i >> 6, k = i & 63;
            ((float4*)(sm + b*SX))[128 + k] = ldcg4(h4 + b*(HD/4) + col/4 + k);
        }
        __syncthreads();
        lstm_phase<768, false>(sm, Ws, bias, jb, g_h1[pr^1] + col, g_c1 + col, nullptr, 0);
        ph++; gbar(&g_cntE1, &g_flagE1, ph, 128);
    }
}

// ---- persistent decoder: 127 steps of (dec0 | dec1 | proj+argmax) in ONE kernel ----
__global__ void __launch_bounds__(512) k_decp(const float* __restrict__ oemb,
        const float* __restrict__ linW, const float* __restrict__ linb,
        float* __restrict__ out) {
    extern __shared__ float sm[];
    const int tid = threadIdx.x, bx = blockIdx.x;
    unsigned ph = 0;
    for (int s = 0; s < OUTC-1; s++) {
        int pr = s & 1;
        // ---------- phase A: dec0 (K = 768) ----------
        {
            constexpr int SX = 772;
            float* Ws = sm + 32*SX;
            for (int i = tid; i < 16*768/4; i += 512)
                ((float4*)Ws)[i] = ((const float4*)(g_Wdec0 + bx*16*768))[i];
            for (int i = tid; i < 32*64; i += 512) {
                int b = i >> 6, k = i & 63;
                unsigned tok = (unsigned)(VOUT-1) - (unsigned)(__ldcg(&g_amax[b]) & 0xFFFFFFFFull);
                ((float4*)(sm + b*SX))[k] = ((const float4*)oemb)[(size_t)tok*64 + k];
            }
            const float4* h4 = (const float4*)(g_h0[pr]);
            for (int i = tid; i < 32*128; i += 512) {
                int b = i >> 7, k = i & 127;
                ((float4*)(sm + b*SX))[64 + k] = ldcg4(h4 + b*128 + k);
            }
            __syncthreads();
            lstm_phase<768, false>(sm, Ws, g_bdec0, bx, g_h0[pr^1], g_c0, nullptr, 0);
            ph++; gbar(&g_cntD, &g_flagD, ph, 128);
        }
        // ---------- phase B: dec1 (K = 1024) ----------
        {
            constexpr int SX = 1028;
            float* Ws = sm + 32*SX;
            for (int i = tid; i < 16*1024/4; i += 512)
                ((float4*)Ws)[i] = ((const float4*)(g_Wdec1 + bx*16*1024))[i];
            const float4* a4 = (const float4*)(g_h0[pr^1]);
            const float4* b4 = (const float4*)(g_h1[pr]);
            for (int i = tid; i < 32*128; i += 512) {
                int b = i >> 7, k = i & 127;
                ((float4*)(sm + b*SX))[k] = ldcg4(a4 + b*128 + k);
            }
            for (int i = tid; i < 32*128; i += 512) {
                int b = i >> 7, k = i & 127;
                ((float4*)(sm + b*SX))[128 + k] = ldcg4(b4 + b*128 + k);
            }
            if (bx == 0 && tid < 32) g_amax[tid] = 0ull;   // safe: nobody reads amax in B
            __syncthreads();
            lstm_phase<1024, false>(sm, Ws, g_bdec1, bx, g_h1[pr^1], g_c1, nullptr, 0);
            ph++; gbar(&g_cntD, &g_flagD, ph, 128);
        }
        // ---------- phase C: projection + fused argmax, column s+1 ----------
        {
            int par = pr ^ 1;
            if (bx < 125) {
                float* hs   = sm;                          // 16384 floats (64KB)
                float* sred = sm + 16384;                  // 4*128*36 floats (72KB)
                ull*   sa   = (ull*)(sm + 16384 + 4*128*36); // 32*133 ull (33.2KB)
                const float4* h4 = (const float4*)(g_h1[par]);
                for (int i = tid; i < 4096; i += 512) ((float4*)hs)[i] = ldcg4(h4 + i);
                __syncthreads();
                const int vl = tid & 127, k2 = tid >> 7;
                const int v = bx*128 + vl;
                const ulonglong2* wr = (const ulonglong2*)(linW + (size_t)v*512) + k2*32;
                const ulonglong2* hp = (const ulonglong2*)hs;
                ull acc[32];
#pragma unroll
                for (int b = 0; b < 32; b++) acc[b] = 0ull;
#pragma unroll 2
                for (int kk = 0; kk < 32; kk++) {
                    ulonglong2 wu = wr[kk];
                    int k4 = k2*32 + kk;
#pragma unroll
                    for (int b = 0; b < 32; b++) {
                        ulonglong2 hu = hp[b*128 + k4];
                        ffma2(acc[b], wu.x, hu.x);
                        ffma2(acc[b], wu.y, hu.y);
                    }
                }
                __syncthreads();
                float* my = sred + (k2*128 + vl)*36;
#pragma unroll
                for (int b = 0; b < 32; b++) my[b] = f2sum(acc[b]);
                __syncthreads();
                if (tid < 128) {
                    int vv = bx*128 + tid;
                    const float* r0 = sred + tid*36;
                    float bia = linb[vv];
                    float* op = out + (size_t)(s+1)*VOUT + vv;
#pragma unroll 4
                    for (int b = 0; b < 32; b++) {
                        float r = r0[b] + r0[128*36 + b] + r0[256*36 + b] + r0[384*36 + b] + bia;
                        op[(size_t)b*OUTC*VOUT] = r;
                        unsigned bits = __float_as_uint(r);
                        unsigned m = (bits & 0x80000000u) ? ~bits : (bits | 0x80000000u);
                        sa[b*133 + tid] = ((ull)m << 32) | (unsigned)(VOUT-1 - vv);
                    }
                }
                __syncthreads();
                if (tid < 32) {
                    ull best = 0;
                    const ull* row = sa + tid*133;
#pragma unroll 4
                    for (int i = 0; i < 128; i++) { ull p = row[i]; if (p > best) best = p; }
                    atomicMax(&g_amax[tid], best);
                }
            }
            ph++; gbar(&g_cntD, &g_flagD, ph, 128);
        }
    }
}

extern "C" void kernel_launch(void* const* d_in, const int* in_sizes, int n_in,
                              void* d_out, int out_size) {
    const int*   inp    = (const int*)d_in[0];
    const int*   cls    = (const int*)d_in[1];
    const float* in_emb = (const float*)d_in[2];
    const float* oemb   = (const float*)d_in[3];
    const float* linW   = (const float*)d_in[22];
    const float* linb   = (const float*)d_in[23];
    float* out = (float*)d_out;

    const int SM_E0 = (32*516 + 16*512) * 4;      // 98816
    const int SM_E1 = (32*772 + 16*768) * 4;      // 147968
    const int SM_D  = (32*1028 + 16*1024) * 4;    // 197120
    cudaFuncSetAttribute(k_enc0p, cudaFuncAttributeMaxDynamicSharedMemorySize, SM_E0);
    cudaFuncSetAttribute(k_enc1p, cudaFuncAttributeMaxDynamicSharedMemorySize, SM_E1);
    cudaFuncSetAttribute(k_decp,  cudaFuncAttributeMaxDynamicSharedMemorySize, SM_D);

    k_prep<<<256,256>>>(0, (const float*)d_in[4],  (const float*)d_in[5],  (const float*)d_in[6],  EE,   H1);
    k_prep<<<256,256>>>(1, (const float*)d_in[7],  (const float*)d_in[8],  (const float*)d_in[9],  EE,   H1);
    k_prep<<<256,256>>>(2, (const float*)d_in[10], (const float*)d_in[11], (const float*)d_in[12], 2*H1, H1);
    k_prep<<<256,256>>>(3, (const float*)d_in[13], (const float*)d_in[14], (const float*)d_in[15], 2*H1, H1);
    k_prep<<<256,256>>>(4, (const float*)d_in[16], (const float*)d_in[17], (const float*)d_in[18], EE,   HD);
    k_prep<<<256,256>>>(5, (const float*)d_in[19], (const float*)d_in[20], (const float*)d_in[21], HD,   HD);

    k_init<<<512,256>>>(out, cls);
    k_embed<<<1024,256>>>(inp, in_emb);

    k_enc0p<<<128, 512, SM_E0>>>();
    k_enc1p<<<128, 512, SM_E1>>>();
    k_decp <<<128, 512, SM_D >>>(oemb, linW, linb, out);
}

// round 11
// speedup vs baseline: 1.4230x; 1.0795x over previous
#include <cuda_runtime.h>
#include <math.h>

#define BB   32
#define SS   128
#define EE   256
#define H1   256
#define HD   512
#define VOUT 16000
#define OUTC 128
typedef unsigned long long ull;

// ---------------- device scratch ----------------
__device__ float g_xs[SS*BB*EE];
__device__ float g_y0[SS*BB*2*H1];
__device__ float g_Wenc0f[4*H1*(EE+H1)], g_Wenc0b[4*H1*(EE+H1)];
__device__ float g_Wenc1f[4*H1*3*H1],    g_Wenc1b[4*H1*3*H1];
__device__ float g_Wdec0[4*HD*(EE+HD)],  g_Wdec1[4*HD*2*HD];
__device__ float g_benc0f[4*H1], g_benc0b[4*H1], g_benc1f[4*H1], g_benc1b[4*H1];
__device__ float g_bdec0[4*HD], g_bdec1[4*HD];
__device__ float4 g_Wt4[128*VOUT];                // transposed linW: [k4][v]
__device__ float g_h0[2][BB*HD], g_h1[2][BB*HD];
__device__ float g_c0[BB*HD],    g_c1[BB*HD];
__device__ ull   g_amax[BB];                      // packed (mono(val)<<32)|(VOUT-1-v)
__device__ unsigned g_cntE0[2], g_flagE0[2], g_cntE1[2], g_flagE1[2];
__device__ unsigned g_cntD, g_flagD;

// ---------------- helpers ----------------
__device__ __forceinline__ void ffma2(ull& d, ull a, ull b) {
    asm("fma.rn.f32x2 %0, %1, %2, %0;" : "+l"(d) : "l"(a), "l"(b));
}
__device__ __forceinline__ float f2sum(ull p) {
    return __uint_as_float((unsigned)p) + __uint_as_float((unsigned)(p >> 32));
}
__device__ __forceinline__ float4 ldcg4(const float4* p) { return __ldcg(p); }

// grid barrier: monotonic counter + flag; counters zeroed by k_init each replay
__device__ __forceinline__ void gbar(unsigned* cnt, unsigned* flag, unsigned ph, unsigned nb) {
    __syncthreads();
    __threadfence();
    if (threadIdx.x == 0) {
        unsigned old = atomicAdd(cnt, 1u);
        if (old == ph * nb - 1u) {
            *(volatile unsigned*)flag = ph;
        } else {
            while (*(volatile unsigned*)flag < ph) __nanosleep(32);
        }
    }
    __syncthreads();
    __threadfence();
}

// ---- weight prep helper: row g*HH+j -> 4j+g, concat [Wih | Whh] along K ----
__device__ void prep_one(float* Wd, float* bd, const float* __restrict__ Wih,
                         const float* __restrict__ Whh, const float* __restrict__ bsrc,
                         int IN, int HH) {
    int K = IN + HH;
    int total = 4*HH*K;
    int stride = gridDim.x * blockDim.x;
    for (int idx = blockIdx.x*blockDim.x + threadIdx.x; idx < total + 4*HH; idx += stride) {
        if (idx < total) {
            int row = idx / K, k = idx - row*K;
            int j = row >> 2, g = row & 3;
            int sr = g*HH + j;
            Wd[idx] = (k < IN) ? Wih[sr*IN + k] : Whh[sr*HH + (k - IN)];
        } else {
            int r = idx - total;
            bd[r] = bsrc[(r & 3)*HH + (r >> 2)];
        }
    }
}

// ---- single prep kernel: 6 LSTM reorders + linW transpose ----
__global__ void k_prep_all(
    const float* w0, const float* u0, const float* b0,
    const float* w1, const float* u1, const float* b1,
    const float* w2, const float* u2, const float* b2,
    const float* w3, const float* u3, const float* b3,
    const float* w4, const float* u4, const float* b4,
    const float* w5, const float* u5, const float* b5,
    const float* linW)
{
    prep_one(g_Wenc0f, g_benc0f, w0, u0, b0, EE,   H1);
    prep_one(g_Wenc0b, g_benc0b, w1, u1, b1, EE,   H1);
    prep_one(g_Wenc1f, g_benc1f, w2, u2, b2, 2*H1, H1);
    prep_one(g_Wenc1b, g_benc1b, w3, u3, b3, 2*H1, H1);
    prep_one(g_Wdec0,  g_bdec0,  w4, u4, b4, EE,   HD);
    prep_one(g_Wdec1,  g_bdec1,  w5, u5, b5, HD,   HD);
    // transpose linW [V][512] -> g_Wt4[k4][v] (float4 of 4 consecutive k)
    const float4* L4 = (const float4*)linW;
    int stride = gridDim.x * blockDim.x;
    for (int idx = blockIdx.x*blockDim.x + threadIdx.x; idx < VOUT*128; idx += stride) {
        int v = idx >> 7, k4 = idx & 127;
        g_Wt4[k4*VOUT + v] = L4[v*128 + k4];
    }
}

// ---- init: out[:,0,:] one-hot(cls), zero states, amax slots = cls, zero barriers ----
__global__ void k_init(float* __restrict__ out, const int* __restrict__ cls) {
    int c = *cls;
    const int N1 = BB*VOUT;
    const int N2 = 4*BB*HD;
    int stride = gridDim.x * blockDim.x;
    if (blockIdx.x == 0 && threadIdx.x == 0) {
        g_cntE0[0]=0; g_cntE0[1]=0; g_flagE0[0]=0; g_flagE0[1]=0;
        g_cntE1[0]=0; g_cntE1[1]=0; g_flagE1[0]=0; g_flagE1[1]=0;
        g_cntD = 0; g_flagD = 0;
    }
    for (int idx = blockIdx.x*blockDim.x + threadIdx.x; idx < N1+N2+BB; idx += stride) {
        if (idx < N1) {
            int b = idx / VOUT, v = idx - b*VOUT;
            out[(size_t)b*OUTC*VOUT + v] = (v == c) ? 1.0f : 0.0f;
        } else if (idx < N1+N2) {
            int r = idx - N1;
            int buf = r / (BB*HD), off = r - buf*(BB*HD);
            float* p = (buf==0) ? g_h0[0] : (buf==1) ? g_h1[0] : (buf==2) ? g_c0 : g_c1;
            p[off] = 0.0f;
        } else {
            g_amax[idx - N1 - N2] = (ull)(unsigned)(VOUT - 1 - c);
        }
    }
}

// ---- embedding gather -> g_xs[t][b][e] ----
__global__ void k_embed(const int* __restrict__ inp, const float* __restrict__ emb) {
    int i = blockIdx.x*256 + threadIdx.x;      // 262144 float4s
    int e4 = i & 63, b = (i >> 6) & 31, t = i >> 11;
    ((float4*)g_xs)[i] = ((const float4*)emb)[(size_t)inp[b*SS + t]*64 + e4];
}

// ---- fused LSTM phase: 16 reordered rows x 32 batch, 4-way K split, f32x2 FMA, cell epilogue ----
template<int K, bool WY>
__device__ __forceinline__ void lstm_phase(
    float* sm, const float* __restrict__ Ws, const float* __restrict__ bias, int jb,
    float* __restrict__ hout, float* __restrict__ cbuf,
    float* __restrict__ y, int ystride)
{
    constexpr int SX = K + 4;
    const int tid = threadIdx.x;
    const int b = tid & 31, q = (tid >> 5) & 3, ks = tid >> 7;
    const ulonglong2* w0 = (const ulonglong2*)(Ws + (q*4+0)*K);
    const ulonglong2* w1 = (const ulonglong2*)(Ws + (q*4+1)*K);
    const ulonglong2* w2 = (const ulonglong2*)(Ws + (q*4+2)*K);
    const ulonglong2* w3 = (const ulonglong2*)(Ws + (q*4+3)*K);
    const ulonglong2* xb = (const ulonglong2*)(sm + b*SX);
    ull a0=0, a1=0, a2=0, a3=0;
    constexpr int KC = K / 16;                 // float4 count per K-slice
    const int k0 = ks * KC;
#pragma unroll 4
    for (int k = k0; k < k0 + KC; ++k) {
        ulonglong2 xv = xb[k];
        ulonglong2 u;
        u = w0[k]; ffma2(a0, u.x, xv.x); ffma2(a0, u.y, xv.y);
        u = w1[k]; ffma2(a1, u.x, xv.x); ffma2(a1, u.y, xv.y);
        u = w2[k]; ffma2(a2, u.x, xv.x); ffma2(a2, u.y, xv.y);
        u = w3[k]; ffma2(a3, u.x, xv.x); ffma2(a3, u.y, xv.y);
    }
    __syncthreads();
    float4* red = (float4*)sm;                 // overlay Xs region (Ws untouched)
    red[ks*128 + q*32 + b] = make_float4(f2sum(a0), f2sum(a1), f2sum(a2), f2sum(a3));
    __syncthreads();
    if (tid < 128) {                           // ks==0 here; (q,b) still valid
        float4 s0=red[tid], s1=red[128+tid], s2=red[256+tid], s3=red[384+tid];
        int j = jb*4 + q;
        float4 bv = ((const float4*)bias)[j];
        float gi=s0.x+s1.x+s2.x+s3.x+bv.x;
        float gf=s0.y+s1.y+s2.y+s3.y+bv.y;
        float gg=s0.z+s1.z+s2.z+s3.z+bv.z;
        float go=s0.w+s1.w+s2.w+s3.w+bv.w;
        float ig=1.f/(1.f+expf(-gi)), fg=1.f/(1.f+expf(-gf));
        float gt=tanhf(gg),           og=1.f/(1.f+expf(-go));
        float c = fg*cbuf[b*HD + j] + ig*gt;
        float h = og*tanhf(c);
        cbuf[b*HD + j] = c;
        hout[b*HD + j] = h;
        if (WY) y[b*ystride + j] = h;
    }
}

// ---- persistent encoder layer 0: 128 blocks = 64 jb x 2 dir, per-dir barriers ----
__global__ void __launch_bounds__(512) k_enc0p() {
    extern __shared__ float sm[];
    constexpr int SX = EE + H1 + 4;            // 516
    float* Ws = sm + 32*SX;
    const int tid = threadIdx.x, bx = blockIdx.x;
    const int jb = bx & 63, dir = bx >> 6, col = dir ? H1 : 0;
    const float* W    = dir ? g_Wenc0b : g_Wenc0f;
    const float* bias = dir ? g_benc0b : g_benc0f;
    for (int i = tid; i < 16*512/4; i += 512)
        ((float4*)Ws)[i] = ((const float4*)(W + jb*16*512))[i];
    unsigned ph = 0;
    for (int t = 0; t < SS; t++) {
        int ts = dir ? SS-1-t : t, pr = t & 1;
        const float4* x4 = (const float4*)(g_xs + ts*BB*EE);
        const float4* h4 = (const float4*)(g_h0[pr]);
        for (int i = tid; i < 32*64; i += 512) {
            int b = i >> 6, k = i & 63;
            ((float4*)(sm + b*SX))[k] = x4[b*64 + k];
        }
        for (int i = tid; i < 32*64; i += 512) {
            int b = i >> 6, k = i & 63;
            ((float4*)(sm + b*SX))[64 + k] = ldcg4(h4 + b*(HD/4) + col/4 + k);
        }
        __syncthreads();
        lstm_phase<512, true>(sm, Ws, bias, jb, g_h0[pr^1] + col, g_c0 + col,
                              g_y0 + ts*BB*2*H1 + col, 2*H1);
        ph++; gbar(&g_cntE0[dir], &g_flagE0[dir], ph, 64);
    }
}

// ---- persistent encoder layer 1 ----
__global__ void __launch_bounds__(512) k_enc1p() {
    extern __shared__ float sm[];
    constexpr int SX = 2*H1 + H1 + 4;          // 772
    float* Ws = sm + 32*SX;
    const int tid = threadIdx.x, bx = blockIdx.x;
    const int jb = bx & 63, dir = bx >> 6, col = dir ? H1 : 0;
    const float* W    = dir ? g_Wenc1b : g_Wenc1f;
    const float* bias = dir ? g_benc1b : g_benc1f;
    for (int i = tid; i < 16*768/4; i += 512)
        ((float4*)Ws)[i] = ((const float4*)(W + jb*16*768))[i];
    unsigned ph = 0;
    for (int t = 0; t < SS; t++) {
        int ts = dir ? SS-1-t : t, pr = t & 1;
        const float4* x4 = (const float4*)(g_y0 + ts*BB*2*H1);
        const float4* h4 = (const float4*)(g_h1[pr]);
        for (int i = tid; i < 32*128; i += 512) {
            int b = i >> 7, k = i & 127;
            ((float4*)(sm + b*SX))[k] = x4[b*128 + k];
        }
        for (int i = tid; i < 32*64; i += 512) {
            int b = i >> 6, k = i & 63;
            ((float4*)(sm + b*SX))[128 + k] = ldcg4(h4 + b*(HD/4) + col/4 + k);
        }
        __syncthreads();
        lstm_phase<768, false>(sm, Ws, bias, jb, g_h1[pr^1] + col, g_c1 + col, nullptr, 0);
        ph++; gbar(&g_cntE1[dir], &g_flagE1[dir], ph, 64);
    }
}

// ---- persistent decoder: 127 steps of (dec0 | dec1 | proj+argmax) in ONE kernel ----
__global__ void __launch_bounds__(512) k_decp(const float* __restrict__ oemb,
        const float* __restrict__ linb, float* __restrict__ out) {
    extern __shared__ float sm[];
    const int tid = threadIdx.x, bx = blockIdx.x;
    unsigned ph = 0;
    for (int s = 0; s < OUTC-1; s++) {
        int pr = s & 1;
        // ---------- phase A: dec0 (K = 768) ----------
        {
            constexpr int SX = 772;
            float* Ws = sm + 32*SX;
            for (int i = tid; i < 16*768/4; i += 512)
                ((float4*)Ws)[i] = ((const float4*)(g_Wdec0 + bx*16*768))[i];
            for (int i = tid; i < 32*64; i += 512) {
                int b = i >> 6, k = i & 63;
                unsigned tok = (unsigned)(VOUT-1) - (unsigned)(__ldcg(&g_amax[b]) & 0xFFFFFFFFull);
                ((float4*)(sm + b*SX))[k] = ((const float4*)oemb)[(size_t)tok*64 + k];
            }
            const float4* h4 = (const float4*)(g_h0[pr]);
            for (int i = tid; i < 32*128; i += 512) {
                int b = i >> 7, k = i & 127;
                ((float4*)(sm + b*SX))[64 + k] = ldcg4(h4 + b*128 + k);
            }
            __syncthreads();
            lstm_phase<768, false>(sm, Ws, g_bdec0, bx, g_h0[pr^1], g_c0, nullptr, 0);
            ph++; gbar(&g_cntD, &g_flagD, ph, 128);
        }
        // ---------- phase B: dec1 (K = 1024) ----------
        {
            constexpr int SX = 1028;
            float* Ws = sm + 32*SX;
            for (int i = tid; i < 16*1024/4; i += 512)
                ((float4*)Ws)[i] = ((const float4*)(g_Wdec1 + bx*16*1024))[i];
            const float4* a4 = (const float4*)(g_h0[pr^1]);
            const float4* b4 = (const float4*)(g_h1[pr]);
            for (int i = tid; i < 32*128; i += 512) {
                int b = i >> 7, k = i & 127;
                ((float4*)(sm + b*SX))[k] = ldcg4(a4 + b*128 + k);
            }
            for (int i = tid; i < 32*128; i += 512) {
                int b = i >> 7, k = i & 127;
                ((float4*)(sm + b*SX))[128 + k] = ldcg4(b4 + b*128 + k);
            }
            if (bx == 0 && tid < 32) g_amax[tid] = 0ull;   // safe: nobody touches amax in B
            __syncthreads();
            lstm_phase<1024, false>(sm, Ws, g_bdec1, bx, g_h1[pr^1], g_c1, nullptr, 0);
            ph++; gbar(&g_cntD, &g_flagD, ph, 128);
        }
        // ---------- phase C: projection + fused argmax, column s+1 ----------
        {
            int par = pr ^ 1;
            if (bx < 125) {
                float* hs   = sm;                            // 16384 floats (64KB)
                float* sred = sm + 16384;                    // 4*128*36 floats (72KB)
                ull*   sa   = (ull*)(sm + 16384 + 4*128*36); // 32*133 ull (33.2KB)
                const float4* h4 = (const float4*)(g_h1[par]);
                for (int i = tid; i < 4096; i += 512) ((float4*)hs)[i] = ldcg4(h4 + i);
                __syncthreads();
                const int vl = tid & 127, k2 = tid >> 7;
                const int v = bx*128 + vl;
                const ulonglong2* wt = (const ulonglong2*)g_Wt4;   // [k4][v] coalesced
                const ulonglong2* hp = (const ulonglong2*)hs;
                ull acc[32];
#pragma unroll
                for (int b = 0; b < 32; b++) acc[b] = 0ull;
#pragma unroll 2
                for (int kk = 0; kk < 32; kk++) {
                    int k4 = k2*32 + kk;
                    ulonglong2 wu = wt[(size_t)k4*VOUT + v];
#pragma unroll
                    for (int b = 0; b < 32; b++) {
                        ulonglong2 hu = hp[b*128 + k4];
                        ffma2(acc[b], wu.x, hu.x);
                        ffma2(acc[b], wu.y, hu.y);
                    }
                }
                __syncthreads();
                float* my = sred + (k2*128 + vl)*36;
#pragma unroll
                for (int b = 0; b < 32; b++) my[b] = f2sum(acc[b]);
                __syncthreads();
                if (tid < 128) {
                    int vv = bx*128 + tid;
                    const float* r0 = sred + tid*36;
                    float bia = linb[vv];
                    float* op = out + (size_t)(s+1)*VOUT + vv;
#pragma unroll 4
                    for (int b = 0; b < 32; b++) {
                        float r = r0[b] + r0[128*36 + b] + r0[256*36 + b] + r0[384*36 + b] + bia;
                        op[(size_t)b*OUTC*VOUT] = r;
                        unsigned bits = __float_as_uint(r);
                        unsigned m = (bits & 0x80000000u) ? ~bits : (bits | 0x80000000u);
                        sa[b*133 + tid] = ((ull)m << 32) | (unsigned)(VOUT-1 - vv);
                    }
                }
                __syncthreads();
                if (tid < 32) {
                    ull best = 0;
                    const ull* row = sa + tid*133;
#pragma unroll 4
                    for (int i = 0; i < 128; i++) { ull p = row[i]; if (p > best) best = p; }
                    atomicMax(&g_amax[tid], best);
                }
            }
            ph++; gbar(&g_cntD, &g_flagD, ph, 128);
        }
    }
}

extern "C" void kernel_launch(void* const* d_in, const int* in_sizes, int n_in,
                              void* d_out, int out_size) {
    const int*   inp    = (const int*)d_in[0];
    const int*   cls    = (const int*)d_in[1];
    const float* in_emb = (const float*)d_in[2];
    const float* oemb   = (const float*)d_in[3];
    const float* linW   = (const float*)d_in[22];
    const float* linb   = (const float*)d_in[23];
    float* out = (float*)d_out;

    const int SM_E0 = (32*516 + 16*512) * 4;      // 98816
    const int SM_E1 = (32*772 + 16*768) * 4;      // 147968
    const int SM_D  = (32*1028 + 16*1024) * 4;    // 197120
    cudaFuncSetAttribute(k_enc0p, cudaFuncAttributeMaxDynamicSharedMemorySize, SM_E0);
    cudaFuncSetAttribute(k_enc1p, cudaFuncAttributeMaxDynamicSharedMemorySize, SM_E1);
    cudaFuncSetAttribute(k_decp,  cudaFuncAttributeMaxDynamicSharedMemorySize, SM_D);

    // launch #1..#6 so ncu (-s 5 -c 1) captures k_decp
    k_prep_all<<<512,256>>>(
        (const float*)d_in[4],  (const float*)d_in[5],  (const float*)d_in[6],
        (const float*)d_in[7],  (const float*)d_in[8],  (const float*)d_in[9],
        (const float*)d_in[10], (const float*)d_in[11], (const float*)d_in[12],
        (const float*)d_in[13], (const float*)d_in[14], (const float*)d_in[15],
        (const float*)d_in[16], (const float*)d_in[17], (const float*)d_in[18],
        (const float*)d_in[19], (const float*)d_in[20], (const float*)d_in[21],
        linW);
    k_init<<<512,256>>>(out, cls);
    k_embed<<<1024,256>>>(inp, in_emb);
    k_enc0p<<<128, 512, SM_E0>>>();
    k_enc1p<<<128, 512, SM_E1>>>();
    k_decp <<<128, 512, SM_D >>>(oemb, linb, out);
}